// round 7
// baseline (speedup 1.0000x reference)
#include <cuda_runtime.h>
#include <cuda_fp16.h>
#include <cstdint>
#include <cstddef>

// ---------------------------------------------------------------------------
// Problem constants
// ---------------------------------------------------------------------------
#define N_TOT 262144
#define CH    128          // C_in = C_out = 128
#define K_OFF 27
#define TM    128          // rows per GEMM tile
#define NBLK  (N_TOT / TM) // 2048
#define NTAP  26           // taps excluding self (k=13)
#define SCAT_GX 17         // CTAs per tap; 17*26=442 CTAs, ~15 tiles each
#define SELF_GRID 296      // 2 CTAs/SM, ~7 tiles each

// A smem: 128 rows x 128 halfs, pitch 136 halfs (272B) -> conflict-free frag LDS
#define A_PITCH_B 272
#define A_BYTES   (TM * A_PITCH_B)          // 34816
#define B_BYTES   32768                     // 128x128 fp16, frag-ordered
#define STG_BYTES 65536                     // 128 rows x 512B int staging
#define SMEM_SCAT (2 * A_BYTES + B_BYTES + STG_BYTES)  // 167936
#define SMEM_SELF (2 * A_BYTES + B_BYTES)              // 102400

// fixed-point accumulation
#define SCALE_F     4194304.0f              // 2^22
#define INV_SCALE_F 2.384185791015625e-07f  // 2^-22

// ---------------------------------------------------------------------------
// Scratch (__device__ globals; no allocations allowed)
// ---------------------------------------------------------------------------
__device__ __half   g_fh[N_TOT * CH];             // fp16 feats (64 MB)
__device__ uint32_t g_Wh[K_OFF * 8192];           // fp16 W, frag-ordered
__device__ int      g_acc[N_TOT * CH];            // int32 fixed-point accumulator
__device__ int2     g_list[(size_t)NTAP * N_TOT]; // per-tap pair lists
__device__ int      g_cnt[NTAP];
__device__ float    g_psum[NBLK * CH];
__device__ float    g_psq [NBLK * CH];
__device__ float    g_scale[CH];
__device__ float    g_shift[CH];

// ---------------------------------------------------------------------------
// helpers
// ---------------------------------------------------------------------------
__device__ __forceinline__ void cp16(uint32_t dst, const void* src, int srcsize) {
    asm volatile("cp.async.cg.shared.global [%0], [%1], 16, %2;"
                 :: "r"(dst), "l"(src), "r"(srcsize) : "memory");
}
__device__ __forceinline__ void cp16f(uint32_t dst, const void* src) {
    asm volatile("cp.async.cg.shared.global [%0], [%1], 16;"
                 :: "r"(dst), "l"(src) : "memory");
}
#define CP_COMMIT() asm volatile("cp.async.commit_group;" ::: "memory")
#define CP_WAIT(n)  asm volatile("cp.async.wait_group %0;" :: "n"(n) : "memory")

// bulk int32 add-reduce: 512B smem row -> global (Hopper+)
__device__ __forceinline__ void red_bulk_512(void* gdst, uint32_t ssrc) {
    asm volatile(
        "cp.reduce.async.bulk.global.shared::cta.bulk_group.add.u32 [%0], [%1], 512;"
        :: "l"(gdst), "r"(ssrc) : "memory");
}
#define BULK_COMMIT() asm volatile("cp.async.bulk.commit_group;" ::: "memory")
#define BULK_WAIT0()  asm volatile("cp.async.bulk.wait_group 0;" ::: "memory")
#define FENCE_PROXY_ASYNC() \
    asm volatile("fence.proxy.async.shared::cta;" ::: "memory")

__device__ __forceinline__ uint32_t smem_u32(const void* p) {
    uint32_t a;
    asm("{ .reg .u64 t; cvta.to.shared.u64 t, %1; cvt.u32.u64 %0, t; }"
        : "=r"(a) : "l"(p));
    return a;
}
__device__ __forceinline__ int f2i(float v) { return __float2int_rn(v * SCALE_F); }

// ---------------------------------------------------------------------------
// Kernel 0a: feats f32 -> fp16
// ---------------------------------------------------------------------------
__global__ __launch_bounds__(256) void prep_feats_kernel(const float* __restrict__ f)
{
    size_t e = (size_t)blockIdx.x * 256 + threadIdx.x;   // one per 8 floats
    const float4* src = (const float4*)f + e * 2;
    float4 v0 = __ldg(&src[0]);
    float4 v1 = __ldg(&src[1]);
    __half2 h0 = __floats2half2_rn(v0.x, v0.y);
    __half2 h1 = __floats2half2_rn(v0.z, v0.w);
    __half2 h2 = __floats2half2_rn(v1.x, v1.y);
    __half2 h3 = __floats2half2_rn(v1.z, v1.w);
    uint4 o;
    o.x = *(uint32_t*)&h0; o.y = *(uint32_t*)&h1;
    o.z = *(uint32_t*)&h2; o.w = *(uint32_t*)&h3;
    ((uint4*)g_fh)[e] = o;
}

// ---------------------------------------------------------------------------
// Kernel 0b: W f32 -> fp16, frag-ordered for mma.m16n8k16 B operand.
//   n = jj*8 + t/4 ; kk = s*16 + (t%4)*2 + r*8  (pair kk, kk+1)
// ---------------------------------------------------------------------------
__global__ __launch_bounds__(256) void prep_w_kernel(const float* __restrict__ W)
{
    int e = blockIdx.x * 256 + threadIdx.x;
    if (e >= K_OFF * 8192) return;
    int k   = e >> 13;
    int rem = e & 8191;
    int s   = rem >> 10;
    int jj  = (rem >> 6) & 15;
    int t   = (rem >> 1) & 31;
    int r   = e & 1;
    int n   = jj * 8 + (t >> 2);
    int kk  = s * 16 + (t & 3) * 2 + r * 8;
    const float* Wk = W + (size_t)k * CH * CH;
    __half2 h = __floats2half2_rn(Wk[kk * CH + n], Wk[(kk + 1) * CH + n]);
    g_Wh[e] = *(uint32_t*)&h;
}

// ---------------------------------------------------------------------------
// Kernel 0c: zero the 26 pair counters
// ---------------------------------------------------------------------------
__global__ void zero_cnt_kernel() {
    if (threadIdx.x < NTAP) g_cnt[threadIdx.x] = 0;
}

// ---------------------------------------------------------------------------
// Kernel 1: build per-tap compacted pair lists (skip self tap k=13).
// ---------------------------------------------------------------------------
__global__ __launch_bounds__(256) void build_kernel(const int* __restrict__ nbr)
{
    const int tid  = threadIdx.x;
    const int lane = tid & 31;
    const int wid  = tid >> 5;
    const int r    = blockIdx.x * 256 + tid;

    __shared__ int s_cnt [NTAP][8];
    __shared__ int s_base[NTAP][8];

    int idx[NTAP];
    unsigned msk[NTAP];
#pragma unroll
    for (int j = 0; j < NTAP; ++j) {
        int k = (j < 13) ? j : j + 1;
        idx[j] = __ldg(&nbr[(size_t)r * K_OFF + k]);
    }
#pragma unroll
    for (int j = 0; j < NTAP; ++j) {
        msk[j] = __ballot_sync(0xffffffffu, idx[j] >= 0);
        if (lane == 0) s_cnt[j][wid] = __popc(msk[j]);
    }
    __syncthreads();
    if (tid < NTAP) {
        int tot = 0, c[8];
#pragma unroll
        for (int w = 0; w < 8; ++w) { c[w] = tot; tot += s_cnt[tid][w]; }
        int base = atomicAdd(&g_cnt[tid], tot);
#pragma unroll
        for (int w = 0; w < 8; ++w) s_base[tid][w] = base + c[w];
    }
    __syncthreads();
#pragma unroll
    for (int j = 0; j < NTAP; ++j) {
        if (idx[j] >= 0) {
            int pos = s_base[j][wid] + __popc(msk[j] & ((1u << lane) - 1));
            g_list[(size_t)j * N_TOT + pos] = make_int2(r, idx[j]);
        }
    }
}

// ---------------------------------------------------------------------------
// MMA compute core: A (pitch 272B) x B (frag-ordered) -> F, 8 k16 steps.
// ---------------------------------------------------------------------------
struct Frag { float a[2][8][4]; };

__device__ __forceinline__ void frag_zero(Frag& F) {
#pragma unroll
    for (int i = 0; i < 2; i++)
#pragma unroll
        for (int j = 0; j < 8; j++)
#pragma unroll
            for (int c = 0; c < 4; c++) F.a[i][j][c] = 0.f;
}

__device__ __forceinline__ void mma_compute(
    const char* Abuf, const char* Bbuf, int tid, Frag& F)
{
    const int lane   = tid & 31;
    const int wid    = tid >> 5;
    const int warp_m = wid & 3;
    const int warp_n = wid >> 2;
    const int gq     = lane >> 2;
    const int tq     = lane & 3;
    const uint32_t* Au = (const uint32_t*)Abuf;              // pitch 68 u32
    const uint32_t* Bu = (const uint32_t*)Bbuf;

#pragma unroll
    for (int s8 = 0; s8 < 8; ++s8) {
        uint32_t a[2][4];
#pragma unroll
        for (int i = 0; i < 2; ++i) {
            const uint32_t* p0 = Au + (warp_m * 32 + i * 16 + gq) * 68 + s8 * 8 + tq;
            a[i][0] = p0[0];
            a[i][1] = p0[8 * 68];
            a[i][2] = p0[4];
            a[i][3] = p0[8 * 68 + 4];
        }
#pragma unroll
        for (int j = 0; j < 8; ++j) {
            const uint2 b = *(const uint2*)(Bu + (s8 * 16 + warp_n * 8 + j) * 64 + lane * 2);
#pragma unroll
            for (int i = 0; i < 2; ++i) {
                asm volatile(
                    "mma.sync.aligned.m16n8k16.row.col.f32.f16.f16.f32 "
                    "{%0,%1,%2,%3}, {%4,%5,%6,%7}, {%8,%9}, {%0,%1,%2,%3};"
                    : "+f"(F.a[i][j][0]), "+f"(F.a[i][j][1]),
                      "+f"(F.a[i][j][2]), "+f"(F.a[i][j][3])
                    : "r"(a[i][0]), "r"(a[i][1]), "r"(a[i][2]), "r"(a[i][3]),
                      "r"(b.x), "r"(b.y));
            }
        }
    }
}

// A gather for one row-half per thread (8 x cp.async 16B), zero-fill idx<0
__device__ __forceinline__ void gather_row(uint32_t dstA, int tid, int idx)
{
    const int p_row  = tid >> 1;
    const int p_half = tid & 1;
    const char* srow = (const char*)g_fh
                     + ((size_t)(idx < 0 ? 0 : idx) << 8) + p_half * 128;
    uint32_t drow = dstA + p_row * A_PITCH_B + p_half * 128;
    int sz = idx < 0 ? 0 : 16;
#pragma unroll
    for (int q = 0; q < 8; ++q) cp16(drow + q * 16, srow + q * 16, sz);
}

// B copy (frag-ordered 32KB for one tap)
__device__ __forceinline__ void load_B(uint32_t dstB, int tid, int tap)
{
    const char* wsrc = (const char*)g_Wh + (size_t)tap * 32768 + tid * 16;
    uint32_t wdst = dstB + tid * 16;
#pragma unroll
    for (int q = 0; q < 8; ++q) cp16f(wdst + q * 4096, wsrc + q * 4096);
}

// ---------------------------------------------------------------------------
// Kernel 2: self-tap dense GEMM, persistent multi-tile, A double-buffered.
// ---------------------------------------------------------------------------
__global__ __launch_bounds__(256, 2) void self_gemm_kernel()
{
    extern __shared__ char smem[];
    const uint32_t sm32 = smem_u32(smem);
    const uint32_t sB   = sm32 + 2 * A_BYTES;
    const int tid = threadIdx.x;

    const int nmy = (NBLK - blockIdx.x + SELF_GRID - 1) / SELF_GRID;

    // prologue: B + A for first tile
    load_B(sB, tid, 13);
    gather_row(sm32, tid, blockIdx.x * TM + (tid >> 1));
    CP_COMMIT();

    for (int i = 0; i < nmy; ++i) {
        const int s    = i & 1;
        const int tile = blockIdx.x + i * SELF_GRID;
        if (i + 1 < nmy) {
            gather_row(sm32 + (s ^ 1) * A_BYTES, tid,
                       (blockIdx.x + (i + 1) * SELF_GRID) * TM + (tid >> 1));
            CP_COMMIT();
            CP_WAIT(1);
        } else {
            CP_WAIT(0);
        }
        __syncthreads();

        Frag F;
        frag_zero(F);
        mma_compute(smem + s * A_BYTES, smem + 2 * A_BYTES, tid, F);

        const int lane   = tid & 31;
        const int wid    = tid >> 5;
        const int warp_m = wid & 3;
        const int warp_n = wid >> 2;
        const int gq     = lane >> 2;
        const int tq     = lane & 3;
#pragma unroll
        for (int ii = 0; ii < 2; ii++) {
            int r0 = tile * TM + warp_m * 32 + ii * 16 + gq;
#pragma unroll
            for (int j = 0; j < 8; j++) {
                int c = warp_n * 64 + j * 8 + 2 * tq;
                *(int2*)&g_acc[(size_t)r0 * CH + c] =
                    make_int2(f2i(F.a[ii][j][0]), f2i(F.a[ii][j][1]));
                *(int2*)&g_acc[(size_t)(r0 + 8) * CH + c] =
                    make_int2(f2i(F.a[ii][j][2]), f2i(F.a[ii][j][3]));
            }
        }
        __syncthreads();   // all reads of A[s] done before iter i+1 gathers into it
    }
}

// ---------------------------------------------------------------------------
// Kernel 3: scatter GEMM, persistent multi-tile per (tap, slice).
// B resident per CTA; A double-buffered; dedicated int staging + bulk reds.
// ---------------------------------------------------------------------------
__global__ __launch_bounds__(256, 1) void scat_gemm_kernel()
{
    extern __shared__ char smem[];
    const uint32_t sm32 = smem_u32(smem);
    const uint32_t sB   = sm32 + 2 * A_BYTES;
    const uint32_t sSTG = sB + B_BYTES;
    const int tid = threadIdx.x;

    const int j   = blockIdx.y;
    const int tap = (j < 13) ? j : j + 1;
    const int nk  = g_cnt[j];
    const int ntile = (nk + TM - 1) / TM;
    const int bx  = blockIdx.x;
    if (bx >= ntile) return;
    const int nmy = (ntile - bx + SCAT_GX - 1) / SCAT_GX;

    const int2* Lj = g_list + (size_t)j * N_TOT;
    __shared__ int s_out[2][TM];

    const int p_row  = tid >> 1;
    const int p_half = tid & 1;

    // prologue: B + first tile's pair list + A gather
    load_B(sB, tid, tap);
    {
        int start = bx * TM;
        int2 p = (start + p_row < nk) ? __ldg(&Lj[start + p_row])
                                      : make_int2(-1, -1);
        if (p_half == 0) s_out[0][p_row] = p.x;
        gather_row(sm32, tid, p.y);
    }
    CP_COMMIT();

    for (int i = 0; i < nmy; ++i) {
        const int s = i & 1;
        if (i + 1 < nmy) {
            int start = (bx + (i + 1) * SCAT_GX) * TM;
            int2 p = (start + p_row < nk) ? __ldg(&Lj[start + p_row])
                                          : make_int2(-1, -1);
            if (p_half == 0) s_out[s ^ 1][p_row] = p.x;
            gather_row(sm32 + (s ^ 1) * A_BYTES, tid, p.y);
            CP_COMMIT();
            CP_WAIT(1);
        } else {
            CP_WAIT(0);
        }
        __syncthreads();

        Frag F;
        frag_zero(F);
        mma_compute(smem + s * A_BYTES, smem + 2 * A_BYTES, tid, F);

        // drain previous tile's bulk reds before re-staging
        if (tid < TM) BULK_WAIT0();
        __syncthreads();

        // stage int32 tile into dedicated staging region
        {
            int* S = (int*)(smem + 2 * A_BYTES + B_BYTES);
            const int lane   = tid & 31;
            const int wid    = tid >> 5;
            const int warp_m = wid & 3;
            const int warp_n = wid >> 2;
            const int gq     = lane >> 2;
            const int tq     = lane & 3;
#pragma unroll
            for (int ii = 0; ii < 2; ii++) {
                int ra = warp_m * 32 + ii * 16 + gq;
#pragma unroll
                for (int jj = 0; jj < 8; jj++) {
                    int c = warp_n * 64 + jj * 8 + 2 * tq;
                    *(int2*)&S[ra * CH + c] =
                        make_int2(f2i(F.a[ii][jj][0]), f2i(F.a[ii][jj][1]));
                    *(int2*)&S[(ra + 8) * CH + c] =
                        make_int2(f2i(F.a[ii][jj][2]), f2i(F.a[ii][jj][3]));
                }
            }
        }
        __syncthreads();
        FENCE_PROXY_ASYNC();

        // one 512B bulk add-reduce per valid output row
        if (tid < TM) {
            int o = s_out[s][tid];
            if (o >= 0)
                red_bulk_512(&g_acc[(size_t)o * CH], sSTG + tid * 512);
            BULK_COMMIT();   // unconditional: keep per-thread group counts aligned
        }
    }

    if (tid < TM) BULK_WAIT0();   // smem must outlive in-flight bulk reads
    __syncthreads();
}

// ---------------------------------------------------------------------------
// Kernel 4: per-tile per-channel partial sum / sumsq from int accumulator
// ---------------------------------------------------------------------------
__global__ __launch_bounds__(128) void colsum_kernel()
{
    const int c = threadIdx.x;
    const int* p = g_acc + (size_t)blockIdx.x * TM * CH;
    float s = 0.f, q = 0.f;
#pragma unroll 8
    for (int r = 0; r < TM; ++r) {
        float v = (float)p[(size_t)r * CH + c] * INV_SCALE_F;
        s += v;
        q += v * v;
    }
    g_psum[blockIdx.x * CH + c] = s;
    g_psq [blockIdx.x * CH + c] = q;
}

// ---------------------------------------------------------------------------
// Kernel 5: reduce partials -> per-channel scale/shift
// ---------------------------------------------------------------------------
__global__ __launch_bounds__(128) void finalize_kernel(
    const float* __restrict__ gamma, const float* __restrict__ beta)
{
    const int c = threadIdx.x;
    float s = 0.f, q = 0.f;
#pragma unroll 4
    for (int b = 0; b < NBLK; ++b) {
        s += g_psum[b * CH + c];
        q += g_psq [b * CH + c];
    }
    const float inv_n = 1.f / (float)N_TOT;
    float mean = s * inv_n;
    float var  = q * inv_n - mean * mean;
    float sc   = gamma[c] * rsqrtf(var + 1e-4f);
    g_scale[c] = sc;
    g_shift[c] = beta[c] - mean * sc;
}

// ---------------------------------------------------------------------------
// Kernel 6: normalize + leaky ReLU, int accumulator -> float out
// ---------------------------------------------------------------------------
__global__ __launch_bounds__(256) void norm_kernel(float* __restrict__ out)
{
    size_t i = (size_t)blockIdx.x * blockDim.x + threadIdx.x;
    int4 a = ((const int4*)g_acc)[i];
    int c = (int)((i << 2) & (CH - 1));
    float4 v;
    v.x = (float)a.x * INV_SCALE_F;
    v.y = (float)a.y * INV_SCALE_F;
    v.z = (float)a.z * INV_SCALE_F;
    v.w = (float)a.w * INV_SCALE_F;
    float y;
    y = v.x * g_scale[c    ] + g_shift[c    ]; v.x = y > 0.f ? y : 0.333f * y;
    y = v.y * g_scale[c + 1] + g_shift[c + 1]; v.y = y > 0.f ? y : 0.333f * y;
    y = v.z * g_scale[c + 2] + g_shift[c + 2]; v.z = y > 0.f ? y : 0.333f * y;
    y = v.w * g_scale[c + 3] + g_shift[c + 3]; v.w = y > 0.f ? y : 0.333f * y;
    ((float4*)out)[i] = v;
}

// ---------------------------------------------------------------------------
// Launch. Inputs (metadata order): feats, W, gamma, beta, neighbor_idx.
// ---------------------------------------------------------------------------
extern "C" void kernel_launch(void* const* d_in, const int* in_sizes, int n_in,
                              void* d_out, int out_size)
{
    const float* feats = (const float*)d_in[0];
    const float* W     = (const float*)d_in[1];
    const float* gamma = (const float*)d_in[2];
    const float* beta  = (const float*)d_in[3];
    const int*   nbr   = (const int*)  d_in[4];
    float*       out   = (float*)d_out;

    cudaFuncSetAttribute(self_gemm_kernel,
                         cudaFuncAttributeMaxDynamicSharedMemorySize, SMEM_SELF);
    cudaFuncSetAttribute(scat_gemm_kernel,
                         cudaFuncAttributeMaxDynamicSharedMemorySize, SMEM_SCAT);

    prep_feats_kernel<<<N_TOT * CH / 8 / 256, 256>>>(feats);
    prep_w_kernel<<<(K_OFF * 8192 + 255) / 256, 256>>>(W);
    zero_cnt_kernel<<<1, 32>>>();
    build_kernel<<<N_TOT / 256, 256>>>(nbr);
    self_gemm_kernel<<<SELF_GRID, 256, SMEM_SELF>>>();
    scat_gemm_kernel<<<dim3(SCAT_GX, NTAP), 256, SMEM_SCAT>>>();
    colsum_kernel<<<NBLK, 128>>>();
    finalize_kernel<<<1, 128>>>(gamma, beta);
    norm_kernel<<<(N_TOT * CH / 4) / 256, 256>>>(out);
}

// round 8
// speedup vs baseline: 1.0323x; 1.0323x over previous
#include <cuda_runtime.h>
#include <cuda_fp16.h>
#include <cstdint>
#include <cstddef>

// ---------------------------------------------------------------------------
// Problem constants
// ---------------------------------------------------------------------------
#define N_TOT 262144
#define CH    128          // C_in = C_out = 128
#define K_OFF 27
#define TM    128          // rows per GEMM tile
#define NBLK  (N_TOT / TM) // 2048
#define NTAP  26           // taps excluding self (k=13)
#define TILES_PER_TAP 320  // expected ~256 tiles/tap; huge margin

// A smem: 128 rows x 128 halfs, pitch 136 halfs (272B) -> conflict-free frag LDS
#define A_PITCH_B 272
#define A_BYTES   (TM * A_PITCH_B)          // 34816
#define B_BYTES   32768                     // 128x128 fp16, frag-ordered
#define SMEM_ALLOC (A_BYTES + B_BYTES)      // 67584 (>= 64KB staging union)

// fixed-point accumulation; per-contribution bias keeps u64 halves carry-free
#define SCALE_F     4194304.0f              // 2^22
#define INV_SCALE_F 2.384185791015625e-07f  // 2^-22
#define BIAS_I      (1 << 26)               // per-contribution per-half bias

// ---------------------------------------------------------------------------
// Scratch (__device__ globals; no allocations allowed)
// ---------------------------------------------------------------------------
__device__ __half    g_fh[N_TOT * CH];             // fp16 feats (64 MB)
__device__ uint32_t  g_Wh[K_OFF * 8192];           // fp16 W, frag-ordered
__device__ uint64_t  g_acc2[(size_t)N_TOT * 64];   // packed ch-pair accumulator
__device__ int       g_vcnt[N_TOT];                // 1 + valid non-self taps
__device__ int2      g_list[(size_t)NTAP * N_TOT]; // per-tap pair lists
__device__ int       g_cnt[NTAP];
__device__ float     g_psum[NBLK * CH];
__device__ float     g_psq [NBLK * CH];
__device__ float     g_scale[CH];
__device__ float     g_shift[CH];

// ---------------------------------------------------------------------------
// helpers
// ---------------------------------------------------------------------------
__device__ __forceinline__ void cp16(uint32_t dst, const void* src, int srcsize) {
    asm volatile("cp.async.cg.shared.global [%0], [%1], 16, %2;"
                 :: "r"(dst), "l"(src), "r"(srcsize) : "memory");
}
__device__ __forceinline__ void cp16f(uint32_t dst, const void* src) {
    asm volatile("cp.async.cg.shared.global [%0], [%1], 16;"
                 :: "r"(dst), "l"(src) : "memory");
}
#define CP_COMMIT() asm volatile("cp.async.commit_group;" ::: "memory")
#define CP_WAIT0()  asm volatile("cp.async.wait_group 0;" ::: "memory")

// bulk u64 add-reduce: 512B smem row (64 x u64) -> global
__device__ __forceinline__ void red_bulk_512_u64(void* gdst, uint32_t ssrc) {
    asm volatile(
        "cp.reduce.async.bulk.global.shared::cta.bulk_group.add.u64 [%0], [%1], 512;"
        :: "l"(gdst), "r"(ssrc) : "memory");
}
#define BULK_COMMIT() asm volatile("cp.async.bulk.commit_group;" ::: "memory")
#define BULK_WAIT0()  asm volatile("cp.async.bulk.wait_group 0;" ::: "memory")
#define FENCE_PROXY_ASYNC() \
    asm volatile("fence.proxy.async.shared::cta;" ::: "memory")

__device__ __forceinline__ uint32_t smem_u32(const void* p) {
    uint32_t a;
    asm("{ .reg .u64 t; cvta.to.shared.u64 t, %1; cvt.u32.u64 %0, t; }"
        : "=r"(a) : "l"(p));
    return a;
}
__device__ __forceinline__ int f2i(float v) { return __float2int_rn(v * SCALE_F); }
// pack two biased int32 halves into one u64 (lo = even channel, hi = odd)
__device__ __forceinline__ uint64_t pack2(int lo, int hi) {
    return (uint64_t)(uint32_t)(lo + BIAS_I)
         | ((uint64_t)(uint32_t)(hi + BIAS_I) << 32);
}

// ---------------------------------------------------------------------------
// Kernel 0a: feats f32 -> fp16
// ---------------------------------------------------------------------------
__global__ __launch_bounds__(256) void prep_feats_kernel(const float* __restrict__ f)
{
    size_t e = (size_t)blockIdx.x * 256 + threadIdx.x;   // one per 8 floats
    const float4* src = (const float4*)f + e * 2;
    float4 v0 = __ldg(&src[0]);
    float4 v1 = __ldg(&src[1]);
    __half2 h0 = __floats2half2_rn(v0.x, v0.y);
    __half2 h1 = __floats2half2_rn(v0.z, v0.w);
    __half2 h2 = __floats2half2_rn(v1.x, v1.y);
    __half2 h3 = __floats2half2_rn(v1.z, v1.w);
    uint4 o;
    o.x = *(uint32_t*)&h0; o.y = *(uint32_t*)&h1;
    o.z = *(uint32_t*)&h2; o.w = *(uint32_t*)&h3;
    ((uint4*)g_fh)[e] = o;
}

// ---------------------------------------------------------------------------
// Kernel 0b: W f32 -> fp16, frag-ordered for mma.m16n8k16 B operand.
//   n = jj*8 + t/4 ; kk = s*16 + (t%4)*2 + r*8  (pair kk, kk+1)
// ---------------------------------------------------------------------------
__global__ __launch_bounds__(256) void prep_w_kernel(const float* __restrict__ W)
{
    int e = blockIdx.x * 256 + threadIdx.x;
    if (e >= K_OFF * 8192) return;
    int k   = e >> 13;
    int rem = e & 8191;
    int s   = rem >> 10;
    int jj  = (rem >> 6) & 15;
    int t   = (rem >> 1) & 31;
    int r   = e & 1;
    int n   = jj * 8 + (t >> 2);
    int kk  = s * 16 + (t & 3) * 2 + r * 8;
    const float* Wk = W + (size_t)k * CH * CH;
    __half2 h = __floats2half2_rn(Wk[kk * CH + n], Wk[(kk + 1) * CH + n]);
    g_Wh[e] = *(uint32_t*)&h;
}

// ---------------------------------------------------------------------------
// Kernel 0c: zero the 26 pair counters
// ---------------------------------------------------------------------------
__global__ void zero_cnt_kernel() {
    if (threadIdx.x < NTAP) g_cnt[threadIdx.x] = 0;
}

// ---------------------------------------------------------------------------
// Kernel 1: build per-tap compacted pair lists + per-row contribution count.
// ---------------------------------------------------------------------------
__global__ __launch_bounds__(256) void build_kernel(const int* __restrict__ nbr)
{
    const int tid  = threadIdx.x;
    const int lane = tid & 31;
    const int wid  = tid >> 5;
    const int r    = blockIdx.x * 256 + tid;

    __shared__ int s_cnt [NTAP][8];
    __shared__ int s_base[NTAP][8];

    int idx[NTAP];
    unsigned msk[NTAP];
    int vcnt = 1;   // self tap always contributes
#pragma unroll
    for (int j = 0; j < NTAP; ++j) {
        int k = (j < 13) ? j : j + 1;
        idx[j] = __ldg(&nbr[(size_t)r * K_OFF + k]);
        vcnt += (idx[j] >= 0);
    }
    g_vcnt[r] = vcnt;
#pragma unroll
    for (int j = 0; j < NTAP; ++j) {
        msk[j] = __ballot_sync(0xffffffffu, idx[j] >= 0);
        if (lane == 0) s_cnt[j][wid] = __popc(msk[j]);
    }
    __syncthreads();
    if (tid < NTAP) {
        int tot = 0, c[8];
#pragma unroll
        for (int w = 0; w < 8; ++w) { c[w] = tot; tot += s_cnt[tid][w]; }
        int base = atomicAdd(&g_cnt[tid], tot);
#pragma unroll
        for (int w = 0; w < 8; ++w) s_base[tid][w] = base + c[w];
    }
    __syncthreads();
#pragma unroll
    for (int j = 0; j < NTAP; ++j) {
        if (idx[j] >= 0) {
            int pos = s_base[j][wid] + __popc(msk[j] & ((1u << lane) - 1));
            g_list[(size_t)j * N_TOT + pos] = make_int2(r, idx[j]);
        }
    }
}

// ---------------------------------------------------------------------------
// Shared GEMM core: gather A (fp16 rows) + frag-ordered B, 8 k16 steps.
// ---------------------------------------------------------------------------
struct Frag { float a[2][8][4]; };

__device__ __forceinline__ void gemm_core(
    const char* smem, uint32_t sm32, int tid,
    const int* s_in, int tap, Frag& F)
{
    const int p_row  = tid >> 1;
    const int p_half = tid & 1;
    // A gather (zero-fill invalid rows)
    {
        int idx = s_in[p_row];
        const char* srow = (const char*)g_fh
                         + ((size_t)(idx < 0 ? 0 : idx) << 8) + p_half * 128;
        uint32_t drow = sm32 + p_row * A_PITCH_B + p_half * 128;
        int sz = idx < 0 ? 0 : 16;
#pragma unroll
        for (int q = 0; q < 8; ++q) cp16(drow + q * 16, srow + q * 16, sz);
    }
    // B copy
    {
        const char* wsrc = (const char*)g_Wh + (size_t)tap * 32768 + tid * 16;
        uint32_t wdst = sm32 + A_BYTES + tid * 16;
#pragma unroll
        for (int q = 0; q < 8; ++q) cp16f(wdst + q * 4096, wsrc + q * 4096);
    }
    CP_COMMIT();
    CP_WAIT0();
    __syncthreads();

    const int lane   = tid & 31;
    const int wid    = tid >> 5;
    const int warp_m = wid & 3;
    const int warp_n = wid >> 2;
    const int gq     = lane >> 2;
    const int tq     = lane & 3;
    const uint32_t* Au = (const uint32_t*)smem;              // pitch 68 u32
    const uint32_t* Bu = (const uint32_t*)(smem + A_BYTES);

#pragma unroll
    for (int s8 = 0; s8 < 8; ++s8) {
        uint32_t a[2][4];
#pragma unroll
        for (int i = 0; i < 2; ++i) {
            const uint32_t* p0 = Au + (warp_m * 32 + i * 16 + gq) * 68 + s8 * 8 + tq;
            a[i][0] = p0[0];
            a[i][1] = p0[8 * 68];
            a[i][2] = p0[4];
            a[i][3] = p0[8 * 68 + 4];
        }
#pragma unroll
        for (int j = 0; j < 8; ++j) {
            const uint2 b = *(const uint2*)(Bu + (s8 * 16 + warp_n * 8 + j) * 64 + lane * 2);
#pragma unroll
            for (int i = 0; i < 2; ++i) {
                asm volatile(
                    "mma.sync.aligned.m16n8k16.row.col.f32.f16.f16.f32 "
                    "{%0,%1,%2,%3}, {%4,%5,%6,%7}, {%8,%9}, {%0,%1,%2,%3};"
                    : "+f"(F.a[i][j][0]), "+f"(F.a[i][j][1]),
                      "+f"(F.a[i][j][2]), "+f"(F.a[i][j][3])
                    : "r"(a[i][0]), "r"(a[i][1]), "r"(a[i][2]), "r"(a[i][3]),
                      "r"(b.x), "r"(b.y));
            }
        }
    }
}

// ---------------------------------------------------------------------------
// Kernel 2: self-tap dense GEMM -> direct biased-packed u64 store
// ---------------------------------------------------------------------------
__global__ __launch_bounds__(256, 2) void self_gemm_kernel()
{
    extern __shared__ char smem[];
    const uint32_t sm32 = smem_u32(smem);
    const int tid  = threadIdx.x;
    const int base = blockIdx.x * TM;

    __shared__ int s_in[TM];
    if (tid < TM) s_in[tid] = base + tid;
    __syncthreads();

    Frag F;
#pragma unroll
    for (int i = 0; i < 2; i++)
#pragma unroll
        for (int j = 0; j < 8; j++)
#pragma unroll
            for (int c = 0; c < 4; c++) F.a[i][j][c] = 0.f;

    gemm_core(smem, sm32, tid, s_in, 13, F);

    const int lane   = tid & 31;
    const int wid    = tid >> 5;
    const int warp_m = wid & 3;
    const int warp_n = wid >> 2;
    const int gq     = lane >> 2;
    const int tq     = lane & 3;
#pragma unroll
    for (int i = 0; i < 2; i++) {
        int r0 = base + warp_m * 32 + i * 16 + gq;
#pragma unroll
        for (int j = 0; j < 8; j++) {
            int c = warp_n * 64 + j * 8 + 2 * tq;   // even channel
            g_acc2[(size_t)r0 * 64 + (c >> 1)] =
                pack2(f2i(F.a[i][j][0]), f2i(F.a[i][j][1]));
            g_acc2[(size_t)(r0 + 8) * 64 + (c >> 1)] =
                pack2(f2i(F.a[i][j][2]), f2i(F.a[i][j][3]));
        }
    }
}

// ---------------------------------------------------------------------------
// Kernel 3: scatter GEMM over compacted pair lists (26 taps).
// Epilogue: stage biased-packed u64 tile in smem; ONE 512B u64 bulk red per row.
// ---------------------------------------------------------------------------
__global__ __launch_bounds__(256, 2) void scat_gemm_kernel()
{
    const int j   = blockIdx.y;
    const int tap = (j < 13) ? j : j + 1;
    const int nk  = g_cnt[j];
    const int start = blockIdx.x * TM;
    if (start >= nk) return;

    extern __shared__ char smem[];
    const uint32_t sm32 = smem_u32(smem);
    const int tid = threadIdx.x;

    __shared__ int s_in[TM];
    __shared__ int s_out[TM];
    if (tid < TM) {
        int2 p = (start + tid < nk)
               ? __ldg(&g_list[(size_t)j * N_TOT + start + tid])
               : make_int2(-1, -1);
        s_out[tid] = p.x;
        s_in [tid] = p.y;
    }
    __syncthreads();

    Frag F;
#pragma unroll
    for (int i = 0; i < 2; i++)
#pragma unroll
        for (int jj = 0; jj < 8; jj++)
#pragma unroll
            for (int c = 0; c < 4; c++) F.a[i][jj][c] = 0.f;

    gemm_core(smem, sm32, tid, s_in, tap, F);
    __syncthreads();   // MMA reads done before smem reuse as staging

    // ---- stage biased u64 tile into smem (overlays A/B region; 64KB)
    uint64_t* S = (uint64_t*)smem;
    const int lane   = tid & 31;
    const int wid    = tid >> 5;
    const int warp_m = wid & 3;
    const int warp_n = wid >> 2;
    const int gq     = lane >> 2;
    const int tq     = lane & 3;
#pragma unroll
    for (int i = 0; i < 2; i++) {
        int ra = warp_m * 32 + i * 16 + gq;
#pragma unroll
        for (int jj = 0; jj < 8; jj++) {
            int c = warp_n * 64 + jj * 8 + 2 * tq;
            S[ra * 64 + (c >> 1)] =
                pack2(f2i(F.a[i][jj][0]), f2i(F.a[i][jj][1]));
            S[(ra + 8) * 64 + (c >> 1)] =
                pack2(f2i(F.a[i][jj][2]), f2i(F.a[i][jj][3]));
        }
    }
    __syncthreads();

    // ---- one 512B u64 bulk add-reduce per valid output row
    if (tid < TM) {
        int o = s_out[tid];
        if (o >= 0) {
            FENCE_PROXY_ASYNC();
            red_bulk_512_u64(&g_acc2[(size_t)o * 64], sm32 + tid * 512);
            BULK_COMMIT();
            BULK_WAIT0();
        }
    }
}

// ---------------------------------------------------------------------------
// Kernel 4: per-tile per-channel partial sum / sumsq (decode biased u64)
// ---------------------------------------------------------------------------
__global__ __launch_bounds__(128) void colsum_kernel()
{
    const int c    = threadIdx.x;
    const int half = c & 1;
    const uint64_t* p = g_acc2 + (size_t)blockIdx.x * TM * 64 + (c >> 1);
    const int* vc = g_vcnt + blockIdx.x * TM;
    float s = 0.f, q = 0.f;
#pragma unroll 4
    for (int r = 0; r < TM; ++r) {
        uint64_t w = p[(size_t)r * 64];
        uint32_t hraw = half ? (uint32_t)(w >> 32) : (uint32_t)w;
        int vi = (int)(hraw - (uint32_t)vc[r] * (uint32_t)BIAS_I);
        float v = (float)vi * INV_SCALE_F;
        s += v;
        q += v * v;
    }
    g_psum[blockIdx.x * CH + c] = s;
    g_psq [blockIdx.x * CH + c] = q;
}

// ---------------------------------------------------------------------------
// Kernel 5: reduce partials -> per-channel scale/shift
// ---------------------------------------------------------------------------
__global__ __launch_bounds__(128) void finalize_kernel(
    const float* __restrict__ gamma, const float* __restrict__ beta)
{
    const int c = threadIdx.x;
    float s = 0.f, q = 0.f;
#pragma unroll 4
    for (int b = 0; b < NBLK; ++b) {
        s += g_psum[b * CH + c];
        q += g_psq [b * CH + c];
    }
    const float inv_n = 1.f / (float)N_TOT;
    float mean = s * inv_n;
    float var  = q * inv_n - mean * mean;
    float sc   = gamma[c] * rsqrtf(var + 1e-4f);
    g_scale[c] = sc;
    g_shift[c] = beta[c] - mean * sc;
}

// ---------------------------------------------------------------------------
// Kernel 6: normalize + leaky ReLU (decode biased u64 -> float out)
// ---------------------------------------------------------------------------
__global__ __launch_bounds__(256) void norm_kernel(float* __restrict__ out)
{
    size_t i = (size_t)blockIdx.x * blockDim.x + threadIdx.x;  // 4 channels
    uint64_t w0 = g_acc2[i * 2];
    uint64_t w1 = g_acc2[i * 2 + 1];
    uint32_t bb = (uint32_t)g_vcnt[i >> 5] * (uint32_t)BIAS_I;
    int c = (int)((i << 2) & (CH - 1));
    float4 v;
    v.x = (float)(int)((uint32_t)w0         - bb) * INV_SCALE_F;
    v.y = (float)(int)((uint32_t)(w0 >> 32) - bb) * INV_SCALE_F;
    v.z = (float)(int)((uint32_t)w1         - bb) * INV_SCALE_F;
    v.w = (float)(int)((uint32_t)(w1 >> 32) - bb) * INV_SCALE_F;
    float y;
    y = v.x * g_scale[c    ] + g_shift[c    ]; v.x = y > 0.f ? y : 0.333f * y;
    y = v.y * g_scale[c + 1] + g_shift[c + 1]; v.y = y > 0.f ? y : 0.333f * y;
    y = v.z * g_scale[c + 2] + g_shift[c + 2]; v.z = y > 0.f ? y : 0.333f * y;
    y = v.w * g_scale[c + 3] + g_shift[c + 3]; v.w = y > 0.f ? y : 0.333f * y;
    ((float4*)out)[i] = v;
}

// ---------------------------------------------------------------------------
// Launch. Inputs (metadata order): feats, W, gamma, beta, neighbor_idx.
// ---------------------------------------------------------------------------
extern "C" void kernel_launch(void* const* d_in, const int* in_sizes, int n_in,
                              void* d_out, int out_size)
{
    const float* feats = (const float*)d_in[0];
    const float* W     = (const float*)d_in[1];
    const float* gamma = (const float*)d_in[2];
    const float* beta  = (const float*)d_in[3];
    const int*   nbr   = (const int*)  d_in[4];
    float*       out   = (float*)d_out;

    cudaFuncSetAttribute(self_gemm_kernel,
                         cudaFuncAttributeMaxDynamicSharedMemorySize, SMEM_ALLOC);
    cudaFuncSetAttribute(scat_gemm_kernel,
                         cudaFuncAttributeMaxDynamicSharedMemorySize, SMEM_ALLOC);

    prep_feats_kernel<<<N_TOT * CH / 8 / 256, 256>>>(feats);
    prep_w_kernel<<<(K_OFF * 8192 + 255) / 256, 256>>>(W);
    zero_cnt_kernel<<<1, 32>>>();
    build_kernel<<<N_TOT / 256, 256>>>(nbr);
    self_gemm_kernel<<<NBLK, 256, SMEM_ALLOC>>>();
    scat_gemm_kernel<<<dim3(TILES_PER_TAP, NTAP), 256, SMEM_ALLOC>>>();
    colsum_kernel<<<NBLK, 128>>>();
    finalize_kernel<<<1, 128>>>(gamma, beta);
    norm_kernel<<<(N_TOT * CH / 4) / 256, 256>>>(out);
}